// round 16
// baseline (speedup 1.0000x reference)
#include <cuda_runtime.h>

#define NQ 300
#define CC 256
#define NH 8
#define HD 32
#define HW 1024
#define HID 512

typedef unsigned long long ull;

// ---------------- packed f32x2 helpers (sm_103a) ----------------
__device__ __forceinline__ ull pk2(float lo, float hi) {
    ull r; asm("mov.b64 %0,{%1,%2};" : "=l"(r) : "f"(lo), "f"(hi)); return r;
}
__device__ __forceinline__ void upk2(ull v, float& lo, float& hi) {
    asm("mov.b64 {%0,%1},%2;" : "=f"(lo), "=f"(hi) : "l"(v));
}
__device__ __forceinline__ ull add2(ull a, ull b) {
    ull r; asm("add.rn.f32x2 %0,%1,%2;" : "=l"(r) : "l"(a), "l"(b)); return r;
}
__device__ __forceinline__ ull mul2(ull a, ull b) {
    ull r; asm("mul.rn.f32x2 %0,%1,%2;" : "=l"(r) : "l"(a), "l"(b)); return r;
}
__device__ __forceinline__ void fma2(ull& d, ull a, ull b) {
    asm("fma.rn.f32x2 %0,%1,%2,%0;" : "+l"(d) : "l"(a), "l"(b));
}

// ---------------- scratch (device globals; no allocation) ----------------
__device__ float g_q[NQ * CC];
__device__ float g_k[HW * CC];
__device__ float g_v[HW * CC];
__device__ float g_s[HID * NQ];       // s[f][q]
__device__ float g_t[HID * HW];       // NEGATED -(W1·key_pos)
__device__ float g_w2n[HID * 8];      // W2 natural rows: [f][h]
__device__ float g_wot[CC * CC];      // Wo transposed
__device__ float g_S[NQ * NH * HW];   // logits + bias (RED), RAW scores [q][h][k]
__device__ float g_rowm[NQ * NH];     // per-row max
__device__ float g_rowinv[NQ * NH];   // per-row 1/sum(exp)
__device__ float g_ctx[NQ * CC];      // ctx partial k[0,512)
__device__ float g_ctx2[NQ * CC];     // ctx partial k[512,1024)

// ---------------- merged prep + QKV: grid 512+296=808 blocks, 128 thr ----------------
__global__ void __launch_bounds__(128) prep_qkv_kernel(const float* __restrict__ ref,
                                                       const float* __restrict__ W1,
                                                       const float* __restrict__ b1,
                                                       const float* __restrict__ W2,
                                                       const float* __restrict__ Wo,
                                                       const float* __restrict__ rq,
                                                       const float* __restrict__ qpos,
                                                       const float* __restrict__ rs,
                                                       const float* __restrict__ sp,
                                                       const float* __restrict__ Wq,
                                                       const float* __restrict__ bq,
                                                       const float* __restrict__ Wk,
                                                       const float* __restrict__ bk,
                                                       const float* __restrict__ Wv,
                                                       const float* __restrict__ bv) {
    __shared__ float As[16][36];
    __shared__ float Bs[16][68];

    int tid = threadIdx.x;

    if (blockIdx.x < 512) {
        // ===== prep path =====
        int f = blockIdx.x;
        float w1x = W1[2 * f], w1y = W1[2 * f + 1], bb = b1[f];
        for (int k = tid; k < HW; k += 128) {
            int kx = k & 31, ky = k >> 5;
            float px = (kx + 0.5f) * (1.0f / 32.0f);
            float py = (ky + 0.5f) * (1.0f / 32.0f);
            g_t[f * HW + k] = -(w1x * px + w1y * py);
        }
        for (int q = tid; q < NQ; q += 128) {
            g_s[f * NQ + q] = w1x * ref[2 * q] + w1y * ref[2 * q + 1] + bb;
        }
        if (tid < NH) {
            g_w2n[f * 8 + tid] = W2[tid * HID + f];
        }
        int idx = blockIdx.x * 128 + tid;
        int r = idx >> 8, c = idx & 255;
        g_wot[c * 256 + r] = Wo[idx];
        return;
    }

    // ===== QKV path =====
    int bxx = blockIdx.x - 512;
    int mt = bxx % 74;
    int n0 = (bxx / 74) * 64;

    const float *A1, *A2, *W, *bias;
    float* out;
    int M, m0;
    if (mt < 10)      { A1 = rq; A2 = qpos; W = Wq; bias = bq; out = g_q; M = NQ; m0 = mt * 32; }
    else if (mt < 42) { A1 = rs; A2 = sp;   W = Wk; bias = bk; out = g_k; M = HW; m0 = (mt - 10) * 32; }
    else              { A1 = rs; A2 = sp;   W = Wv; bias = bv; out = g_v; M = HW; m0 = (mt - 42) * 32; }

    int t = tid;
    int tx = t & 15, ty = t >> 4;
    int r = t >> 2, c4 = t & 3;

    ull acc2[4][2];
#pragma unroll
    for (int i = 0; i < 4; ++i) { acc2[i][0] = 0ull; acc2[i][1] = 0ull; }

    for (int kc = 0; kc < 256; kc += 16) {
        {
            int gm = m0 + r;
            if (gm >= M) gm = M - 1;
            float4 a = *(const float4*)&A1[gm * 256 + kc + c4 * 4];
            float4 a2 = *(const float4*)&A2[gm * 256 + kc + c4 * 4];
            a.x += a2.x; a.y += a2.y; a.z += a2.z; a.w += a2.w;
            As[c4 * 4 + 0][r] = a.x;
            As[c4 * 4 + 1][r] = a.y;
            As[c4 * 4 + 2][r] = a.z;
            As[c4 * 4 + 3][r] = a.w;
        }
#pragma unroll
        for (int it = 0; it < 2; ++it) {
            int rb = r + it * 32;
            float4 b = *(const float4*)&W[(n0 + rb) * 256 + kc + c4 * 4];
            Bs[c4 * 4 + 0][rb] = b.x;
            Bs[c4 * 4 + 1][rb] = b.y;
            Bs[c4 * 4 + 2][rb] = b.z;
            Bs[c4 * 4 + 3][rb] = b.w;
        }
        __syncthreads();

#pragma unroll
        for (int kk = 0; kk < 16; ++kk) {
            float4 av = *(const float4*)&As[kk][ty * 4];
            ulonglong2 bp = *(const ulonglong2*)&Bs[kk][tx * 4];
            ull a0 = pk2(av.x, av.x), a1 = pk2(av.y, av.y);
            ull a2p = pk2(av.z, av.z), a3 = pk2(av.w, av.w);
            fma2(acc2[0][0], a0, bp.x); fma2(acc2[0][1], a0, bp.y);
            fma2(acc2[1][0], a1, bp.x); fma2(acc2[1][1], a1, bp.y);
            fma2(acc2[2][0], a2p, bp.x); fma2(acc2[2][1], a2p, bp.y);
            fma2(acc2[3][0], a3, bp.x); fma2(acc2[3][1], a3, bp.y);
        }
        __syncthreads();
    }

    float4 b4 = *(const float4*)&bias[n0 + tx * 4];
#pragma unroll
    for (int i = 0; i < 4; ++i) {
        int gm = m0 + ty * 4 + i;
        if (gm < M) {
            float4 o;
            upk2(acc2[i][0], o.x, o.y);
            upk2(acc2[i][1], o.z, o.w);
            o.x += b4.x; o.y += b4.y; o.z += b4.z; o.w += b4.w;
            *(float4*)&out[gm * 256 + n0 + tx * 4] = o;
        }
    }
}

// ---------------- logits: g_S = scale * q.k  (8q x 64k, 128 thr) ----------------
__global__ void __launch_bounds__(128) logits_kernel() {
    __shared__ float sm_qT[64 * 8];
    __shared__ float sm_kT[64 * 64];

    int k0 = blockIdx.x * 64;
    int q0 = blockIdx.y * 8;
    int t = threadIdx.x;
    int qp = t >> 5;
    int kg = t & 31;

    ull acc[2][8];
#pragma unroll
    for (int i = 0; i < 2; ++i)
#pragma unroll
        for (int h = 0; h < 8; ++h) acc[i][h] = 0ull;

#pragma unroll
    for (int c = 0; c < 4; ++c) {
#pragma unroll
        for (int j = 0; j < 4; ++j) {
            int idx = t + j * 128;
            int d = idx >> 3, ql = idx & 7;
            int gq = q0 + ql; if (gq > NQ - 1) gq = NQ - 1;
            sm_qT[d * 8 + ql] = g_q[gq * 256 + c * 64 + d];
        }
#pragma unroll
        for (int j = 0; j < 8; ++j) {
            int idx = t + j * 128;
            int d4 = idx >> 6, kr = idx & 63;
            float4 b = *(const float4*)&g_k[(k0 + kr) * 256 + c * 64 + d4 * 4];
            sm_kT[(d4 * 4 + 0) * 64 + kr] = b.x;
            sm_kT[(d4 * 4 + 1) * 64 + kr] = b.y;
            sm_kT[(d4 * 4 + 2) * 64 + kr] = b.z;
            sm_kT[(d4 * 4 + 3) * 64 + kr] = b.w;
        }
        __syncthreads();

#pragma unroll
        for (int half = 0; half < 2; ++half) {
            int h = c * 2 + half;
#pragma unroll 8
            for (int dl = 0; dl < 32; ++dl) {
                int d = half * 32 + dl;
                ull sv2 = *(const ull*)&sm_qT[d * 8 + qp * 2];
                float s0, s1; upk2(sv2, s0, s1);
                ull kp = *(const ull*)&sm_kT[d * 64 + kg * 2];
                fma2(acc[0][h], pk2(s0, s0), kp);
                fma2(acc[1][h], pk2(s1, s1), kp);
            }
        }
        __syncthreads();
    }

    const float scale = 0.17677669529663688f;
    ull sc = pk2(scale, scale);
#pragma unroll
    for (int i = 0; i < 2; ++i) {
        int gq = q0 + qp * 2 + i;
        if (gq < NQ) {
#pragma unroll
            for (int h = 0; h < 8; ++h) {
                ull v = mul2(acc[i][h], sc);
                float lo, hi; upk2(v, lo, hi);
                float2 o = {lo, hi};
                *(float2*)&g_S[(gq * 8 + h) * HW + k0 + kg * 2] = o;
            }
        }
    }
}

// ---------------- bias: h-pair inner loop (unroll 8), RED-add into g_S (R14, frozen) ----------------
__global__ void __launch_bounds__(128, 8) bias_kernel() {
    __shared__ float sm_s[64 * 8];   // [64f][8q]
    __shared__ float sm_t[64 * 64];  // [64f][64k] (negated t)
    __shared__ float sm_w[64 * 8];   // [64f][8h] natural W2 rows

    int k0 = blockIdx.x * 64;
    int q0 = blockIdx.y * 8;
    int fbase = blockIdx.z * 256;

    int t = threadIdx.x;
    int qp = t >> 5;
    int kg = t & 31;

    ulonglong2 acc_[2][2][2];
#pragma unroll
    for (int qi = 0; qi < 2; ++qi)
#pragma unroll
        for (int ki = 0; ki < 2; ++ki)
#pragma unroll
            for (int hh = 0; hh < 2; ++hh) { acc_[qi][ki][hh].x = 0ull; acc_[qi][ki][hh].y = 0ull; }

    for (int fc = 0; fc < 4; ++fc) {
        int f0 = fbase + fc * 64;
#pragma unroll
        for (int j = 0; j < 4; ++j) {
            int idx = t + j * 128;
            int fr = idx >> 3, ql = idx & 7;
            int gq = q0 + ql; if (gq > NQ - 1) gq = NQ - 1;
            sm_s[fr * 8 + ql] = g_s[(f0 + fr) * NQ + gq];
        }
#pragma unroll
        for (int j = 0; j < 8; ++j) {
            int idx = t + j * 128;
            int fr = idx >> 4, k4 = idx & 15;
            *(float4*)&sm_t[fr * 64 + k4 * 4] =
                *(const float4*)&g_t[(f0 + fr) * HW + k0 + k4 * 4];
        }
        {
            int fr = t >> 1, part = t & 1;
            *(float4*)&sm_w[fr * 8 + part * 4] =
                *(const float4*)&g_w2n[(f0 + fr) * 8 + part * 4];
        }
        __syncthreads();

#pragma unroll 8
        for (int fl = 0; fl < 64; ++fl) {
            ull sv2 = *(const ull*)&sm_s[fl * 8 + qp * 2];
            float s0, s1; upk2(sv2, s0, s1);
            ull tp = *(const ull*)&sm_t[fl * 64 + kg * 2];
            ull xa = add2(pk2(s0, s0), tp);
            ull xb = add2(pk2(s1, s1), tp);
            float x00, x01, x10, x11;
            upk2(xa, x00, x01);
            upk2(xb, x10, x11);
            x00 = fmaxf(x00, 0.0f); x01 = fmaxf(x01, 0.0f);
            x10 = fmaxf(x10, 0.0f); x11 = fmaxf(x11, 0.0f);
            ull xs00 = pk2(x00, x00), xs01 = pk2(x01, x01);
            ull xs10 = pk2(x10, x10), xs11 = pk2(x11, x11);
            ulonglong2 wA = *(const ulonglong2*)&sm_w[fl * 8];
            ulonglong2 wB = *(const ulonglong2*)&sm_w[fl * 8 + 4];
            fma2(acc_[0][0][0].x, xs00, wA.x); fma2(acc_[0][0][0].y, xs00, wA.y);
            fma2(acc_[0][0][1].x, xs00, wB.x); fma2(acc_[0][0][1].y, xs00, wB.y);
            fma2(acc_[0][1][0].x, xs01, wA.x); fma2(acc_[0][1][0].y, xs01, wA.y);
            fma2(acc_[0][1][1].x, xs01, wB.x); fma2(acc_[0][1][1].y, xs01, wB.y);
            fma2(acc_[1][0][0].x, xs10, wA.x); fma2(acc_[1][0][0].y, xs10, wA.y);
            fma2(acc_[1][0][1].x, xs10, wB.x); fma2(acc_[1][0][1].y, xs10, wB.y);
            fma2(acc_[1][1][0].x, xs11, wA.x); fma2(acc_[1][1][0].y, xs11, wA.y);
            fma2(acc_[1][1][1].x, xs11, wB.x); fma2(acc_[1][1][1].y, xs11, wB.y);
        }
        __syncthreads();
    }

#pragma unroll
    for (int qi = 0; qi < 2; ++qi) {
        int gq = q0 + qp * 2 + qi;
        if (gq < NQ) {
#pragma unroll
            for (int ki = 0; ki < 2; ++ki) {
                int gk = k0 + kg * 2 + ki;
                float hv[8];
                upk2(acc_[qi][ki][0].x, hv[0], hv[1]);
                upk2(acc_[qi][ki][0].y, hv[2], hv[3]);
                upk2(acc_[qi][ki][1].x, hv[4], hv[5]);
                upk2(acc_[qi][ki][1].y, hv[6], hv[7]);
#pragma unroll
                for (int h = 0; h < 8; ++h) {
                    atomicAdd(&g_S[(gq * 8 + h) * HW + gk], hv[h]);
                }
            }
        }
    }
}

// ---------------- stats: per-row max + 1/sum(exp); reads g_S, writes 2 floats/row ----------------
__global__ void __launch_bounds__(256) stats_kernel() {
    int q = blockIdx.x;
    int warp = threadIdx.x >> 5, lane = threadIdx.x & 31;
    const float4* rp = (const float4*)&g_S[(q * 8 + warp) * 1024];

    float4 r[8];
#pragma unroll
    for (int j = 0; j < 8; ++j) r[j] = rp[lane + 32 * j];

    float m = -1e30f;
#pragma unroll
    for (int j = 0; j < 8; ++j) {
        m = fmaxf(m, fmaxf(fmaxf(r[j].x, r[j].y), fmaxf(r[j].z, r[j].w)));
    }
#pragma unroll
    for (int o = 16; o; o >>= 1) m = fmaxf(m, __shfl_xor_sync(0xffffffffu, m, o));

    float s = 0.0f;
#pragma unroll
    for (int j = 0; j < 8; ++j) {
        s += __expf(r[j].x - m);
        s += __expf(r[j].y - m);
        s += __expf(r[j].z - m);
        s += __expf(r[j].w - m);
    }
#pragma unroll
    for (int o = 16; o; o >>= 1) s += __shfl_xor_sync(0xffffffffu, s, o);

    if (lane == 0) {
        g_rowm[q * 8 + warp] = m;
        g_rowinv[q * 8 + warp] = 1.0f / s;
    }
}

// ---------------- PV with exp-at-staging, k-split via z: grid (4, 38, 2) ----------------
__global__ void __launch_bounds__(128) pv_kernel() {
    __shared__ float Psm[16 * 64];
    __shared__ float vsm[64 * 64];
    __shared__ float rowm[16];
    __shared__ float rowinv[16];

    int by = blockIdx.x;
    int q0 = blockIdx.y * 8;
    int zc = blockIdx.z;
    float* ctx = (zc == 0) ? g_ctx : g_ctx2;
    int t = threadIdx.x;
    int qg = t >> 5;
    int cp = t & 31;
    int h = cp >> 4;
    int cpl = cp & 15;

    // load the 16 row stats (row = hh*8 + q_l)
    if (t < 16) {
        int q_l = t & 7, hh = t >> 3;
        int gq = q0 + q_l; if (gq > NQ - 1) gq = NQ - 1;
        rowm[t] = g_rowm[gq * 8 + 2 * by + hh];
        rowinv[t] = g_rowinv[gq * 8 + 2 * by + hh];
    }
    __syncthreads();

    ull acc2[2] = {0ull, 0ull};

    for (int kc = zc * 512; kc < zc * 512 + 512; kc += 64) {
#pragma unroll
        for (int it = 0; it < 2; ++it) {
            int idx = t + it * 128;
            int row = idx >> 4, kk4 = idx & 15;
            int q_l = row & 7, hh = row >> 3;
            int gq = q0 + q_l; if (gq > NQ - 1) gq = NQ - 1;
            float4 v = *(const float4*)&g_S[(gq * 8 + 2 * by + hh) * 1024 + kc + kk4 * 4];
            float m = rowm[row], inv = rowinv[row];
            float4 e;
            e.x = __expf(v.x - m) * inv;
            e.y = __expf(v.y - m) * inv;
            e.z = __expf(v.z - m) * inv;
            e.w = __expf(v.w - m) * inv;
            *(float4*)&Psm[row * 64 + kk4 * 4] = e;
        }
#pragma unroll
        for (int it = 0; it < 8; ++it) {
            int idx = t + it * 128;
            int row = idx >> 4, c4 = idx & 15;
            *(float4*)&vsm[row * 64 + c4 * 4] =
                *(const float4*)&g_v[(kc + row) * 256 + by * 64 + c4 * 4];
        }
        __syncthreads();

#pragma unroll 4
        for (int kk = 0; kk < 64; kk += 4) {
            float4 p0 = *(const float4*)&Psm[(h * 8 + qg * 2 + 0) * 64 + kk];
            float4 p1 = *(const float4*)&Psm[(h * 8 + qg * 2 + 1) * 64 + kk];
            float p0a[4] = {p0.x, p0.y, p0.z, p0.w};
            float p1a[4] = {p1.x, p1.y, p1.z, p1.w};
#pragma unroll
            for (int j = 0; j < 4; ++j) {
                ull vv = *(const ull*)&vsm[(kk + j) * 64 + h * 32 + cpl * 2];
                fma2(acc2[0], pk2(p0a[j], p0a[j]), vv);
                fma2(acc2[1], pk2(p1a[j], p1a[j]), vv);
            }
        }
        __syncthreads();
    }

#pragma unroll
    for (int i = 0; i < 2; ++i) {
        int gq = q0 + qg * 2 + i;
        if (gq < NQ) {
            float lo, hi;
            upk2(acc2[i], lo, hi);
            float2 o = {lo, hi};
            *(float2*)&ctx[gq * 256 + by * 64 + h * 32 + cpl * 2] = o;
        }
    }
}

// ---------------- out-proj GEMM: out = (ctxA + ctxB) @ WoT + bo ----------------
__global__ void __launch_bounds__(128) outproj_kernel(const float* __restrict__ bo,
                                                      float* __restrict__ out) {
    __shared__ float Csm[8 * 64];
    __shared__ float wsm[64 * 64];

    int by = blockIdx.x;
    int q0 = blockIdx.y * 8;
    int t = threadIdx.x;
    int qg = t >> 5;
    int cp = t & 31;

    ull acc2[2] = {0ull, 0ull};

    for (int kc = 0; kc < 256; kc += 64) {
        {
            int row = t >> 4, kk4 = t & 15;
            int gq = q0 + row; if (gq > NQ - 1) gq = NQ - 1;
            float4 a = *(const float4*)&g_ctx[gq * 256 + kc + kk4 * 4];
            float4 b = *(const float4*)&g_ctx2[gq * 256 + kc + kk4 * 4];
            a.x += b.x; a.y += b.y; a.z += b.z; a.w += b.w;
            *(float4*)&Csm[row * 64 + kk4 * 4] = a;
        }
#pragma unroll
        for (int it = 0; it < 8; ++it) {
            int idx = t + it * 128;
            int row = idx >> 4, c4 = idx & 15;
            *(float4*)&wsm[row * 64 + c4 * 4] =
                *(const float4*)&g_wot[(kc + row) * 256 + by * 64 + c4 * 4];
        }
        __syncthreads();

#pragma unroll 4
        for (int kk = 0; kk < 64; kk += 4) {
            float4 c0 = *(const float4*)&Csm[(qg * 2 + 0) * 64 + kk];
            float4 c1 = *(const float4*)&Csm[(qg * 2 + 1) * 64 + kk];
            float c0a[4] = {c0.x, c0.y, c0.z, c0.w};
            float c1a[4] = {c1.x, c1.y, c1.z, c1.w};
#pragma unroll
            for (int j = 0; j < 4; ++j) {
                ull ww = *(const ull*)&wsm[(kk + j) * 64 + cp * 2];
                fma2(acc2[0], pk2(c0a[j], c0a[j]), ww);
                fma2(acc2[1], pk2(c1a[j], c1a[j]), ww);
            }
        }
        __syncthreads();
    }

    float b0 = bo[by * 64 + cp * 2], b1 = bo[by * 64 + cp * 2 + 1];
#pragma unroll
    for (int i = 0; i < 2; ++i) {
        int gq = q0 + qg * 2 + i;
        if (gq < NQ) {
            float lo, hi;
            upk2(acc2[i], lo, hi);
            float2 o = {lo + b0, hi + b1};
            *(float2*)&out[gq * 256 + cp * 2 + by * 64] = o;
        }
    }
}

// ---------------- launch ----------------
extern "C" void kernel_launch(void* const* d_in, const int* in_sizes, int n_in,
                              void* d_out, int out_size) {
    const float* raw_query = (const float*)d_in[0];
    const float* query_pos = (const float*)d_in[1];
    const float* ref_pts   = (const float*)d_in[2];
    const float* raw_src   = (const float*)d_in[3];
    const float* src_pos   = (const float*)d_in[4];
    const float* Wq = (const float*)d_in[5];
    const float* bq = (const float*)d_in[6];
    const float* Wk = (const float*)d_in[7];
    const float* bk = (const float*)d_in[8];
    const float* Wv = (const float*)d_in[9];
    const float* bv = (const float*)d_in[10];
    const float* Wo = (const float*)d_in[11];
    const float* bo = (const float*)d_in[12];
    const float* W1 = (const float*)d_in[13];
    const float* b1 = (const float*)d_in[14];
    const float* W2 = (const float*)d_in[15];
    float* out = (float*)d_out;

    prep_qkv_kernel<<<808, 128>>>(ref_pts, W1, b1, W2, Wo,
                                  raw_query, query_pos, raw_src, src_pos,
                                  Wq, bq, Wk, bk, Wv, bv);          // 1

    logits_kernel<<<dim3(16, 38), 128>>>();                         // 2

    bias_kernel<<<dim3(16, 38, 2), 128>>>();                        // 3 (REDs into g_S)

    stats_kernel<<<300, 256>>>();                                   // 4 <- ncu capture

    pv_kernel<<<dim3(4, 38, 2), 128>>>();                           // 5 (exp at staging)

    outproj_kernel<<<dim3(4, 38), 128>>>(bo, out);                  // 6
}

// round 17
// speedup vs baseline: 1.0750x; 1.0750x over previous
#include <cuda_runtime.h>

#define NQ 300
#define CC 256
#define NH 8
#define HD 32
#define HW 1024
#define HID 512

typedef unsigned long long ull;

// ---------------- packed f32x2 helpers (sm_103a) ----------------
__device__ __forceinline__ ull pk2(float lo, float hi) {
    ull r; asm("mov.b64 %0,{%1,%2};" : "=l"(r) : "f"(lo), "f"(hi)); return r;
}
__device__ __forceinline__ void upk2(ull v, float& lo, float& hi) {
    asm("mov.b64 {%0,%1},%2;" : "=f"(lo), "=f"(hi) : "l"(v));
}
__device__ __forceinline__ ull add2(ull a, ull b) {
    ull r; asm("add.rn.f32x2 %0,%1,%2;" : "=l"(r) : "l"(a), "l"(b)); return r;
}
__device__ __forceinline__ ull mul2(ull a, ull b) {
    ull r; asm("mul.rn.f32x2 %0,%1,%2;" : "=l"(r) : "l"(a), "l"(b)); return r;
}
__device__ __forceinline__ void fma2(ull& d, ull a, ull b) {
    asm("fma.rn.f32x2 %0,%1,%2,%0;" : "+l"(d) : "l"(a), "l"(b));
}

// ---------------- scratch (device globals; no allocation) ----------------
__device__ float g_q[NQ * CC];
__device__ float g_k[HW * CC];
__device__ float g_v[HW * CC];
__device__ float g_s[HID * NQ];       // s[f][q]
__device__ float g_t[HID * HW];       // NEGATED -(W1·key_pos)
__device__ float g_w2n[HID * 8];      // W2 natural rows: [f][h]
__device__ float g_wot[CC * CC];      // Wo transposed
__device__ float g_S[NQ * NH * HW];   // logits -> probs, [q][h][k]
__device__ float g_B[NQ * NH * HW];   // bias f[0,256),  [q][h][k]
__device__ float g_B2[NQ * NH * HW];  // bias f[256,512), [q][h][k]
__device__ float g_ctx[NQ * CC];      // ctx partial k[0,512)
__device__ float g_ctx2[NQ * CC];     // ctx partial k[512,1024)

// ---------------- prep: tables (feeds BOTH branches of the fork) ----------------
__global__ void __launch_bounds__(128) prep_kernel(const float* __restrict__ ref,
                                                   const float* __restrict__ W1,
                                                   const float* __restrict__ b1,
                                                   const float* __restrict__ W2,
                                                   const float* __restrict__ Wo) {
    int f = blockIdx.x;
    int tid = threadIdx.x;
    float w1x = W1[2 * f], w1y = W1[2 * f + 1], bb = b1[f];
    for (int k = tid; k < HW; k += 128) {
        int kx = k & 31, ky = k >> 5;
        float px = (kx + 0.5f) * (1.0f / 32.0f);
        float py = (ky + 0.5f) * (1.0f / 32.0f);
        g_t[f * HW + k] = -(w1x * px + w1y * py);
    }
    for (int q = tid; q < NQ; q += 128) {
        g_s[f * NQ + q] = w1x * ref[2 * q] + w1y * ref[2 * q + 1] + bb;
    }
    if (tid < NH) {
        g_w2n[f * 8 + tid] = W2[tid * HID + f];
    }
    int idx = blockIdx.x * 128 + tid;
    int r = idx >> 8, c = idx & 255;
    g_wot[c * 256 + r] = Wo[idx];
}

// ---------------- QKV projections: 32m x 64n tiles, 128 threads ----------------
__global__ void __launch_bounds__(128) qkv_gemm_kernel(const float* __restrict__ rq,
                                                       const float* __restrict__ qp,
                                                       const float* __restrict__ rs,
                                                       const float* __restrict__ sp,
                                                       const float* __restrict__ Wq,
                                                       const float* __restrict__ bq,
                                                       const float* __restrict__ Wk,
                                                       const float* __restrict__ bk,
                                                       const float* __restrict__ Wv,
                                                       const float* __restrict__ bv) {
    __shared__ float As[16][36];
    __shared__ float Bs[16][68];

    int mt = blockIdx.x;
    int n0 = blockIdx.y * 64;

    const float *A1, *A2, *W, *bias;
    float* out;
    int M, m0;
    if (mt < 10)      { A1 = rq; A2 = qp; W = Wq; bias = bq; out = g_q; M = NQ; m0 = mt * 32; }
    else if (mt < 42) { A1 = rs; A2 = sp; W = Wk; bias = bk; out = g_k; M = HW; m0 = (mt - 10) * 32; }
    else              { A1 = rs; A2 = sp; W = Wv; bias = bv; out = g_v; M = HW; m0 = (mt - 42) * 32; }

    int t = threadIdx.x;
    int tx = t & 15, ty = t >> 4;
    int r = t >> 2, c4 = t & 3;

    ull acc2[4][2];
#pragma unroll
    for (int i = 0; i < 4; ++i) { acc2[i][0] = 0ull; acc2[i][1] = 0ull; }

    for (int kc = 0; kc < 256; kc += 16) {
        {
            int gm = m0 + r;
            if (gm >= M) gm = M - 1;
            float4 a = *(const float4*)&A1[gm * 256 + kc + c4 * 4];
            float4 a2 = *(const float4*)&A2[gm * 256 + kc + c4 * 4];
            a.x += a2.x; a.y += a2.y; a.z += a2.z; a.w += a2.w;
            As[c4 * 4 + 0][r] = a.x;
            As[c4 * 4 + 1][r] = a.y;
            As[c4 * 4 + 2][r] = a.z;
            As[c4 * 4 + 3][r] = a.w;
        }
#pragma unroll
        for (int it = 0; it < 2; ++it) {
            int rb = r + it * 32;
            float4 b = *(const float4*)&W[(n0 + rb) * 256 + kc + c4 * 4];
            Bs[c4 * 4 + 0][rb] = b.x;
            Bs[c4 * 4 + 1][rb] = b.y;
            Bs[c4 * 4 + 2][rb] = b.z;
            Bs[c4 * 4 + 3][rb] = b.w;
        }
        __syncthreads();

#pragma unroll
        for (int kk = 0; kk < 16; ++kk) {
            float4 av = *(const float4*)&As[kk][ty * 4];
            ulonglong2 bp = *(const ulonglong2*)&Bs[kk][tx * 4];
            ull a0 = pk2(av.x, av.x), a1 = pk2(av.y, av.y);
            ull a2p = pk2(av.z, av.z), a3 = pk2(av.w, av.w);
            fma2(acc2[0][0], a0, bp.x); fma2(acc2[0][1], a0, bp.y);
            fma2(acc2[1][0], a1, bp.x); fma2(acc2[1][1], a1, bp.y);
            fma2(acc2[2][0], a2p, bp.x); fma2(acc2[2][1], a2p, bp.y);
            fma2(acc2[3][0], a3, bp.x); fma2(acc2[3][1], a3, bp.y);
        }
        __syncthreads();
    }

    float4 b4 = *(const float4*)&bias[n0 + tx * 4];
#pragma unroll
    for (int i = 0; i < 4; ++i) {
        int gm = m0 + ty * 4 + i;
        if (gm < M) {
            float4 o;
            upk2(acc2[i][0], o.x, o.y);
            upk2(acc2[i][1], o.z, o.w);
            o.x += b4.x; o.y += b4.y; o.z += b4.z; o.w += b4.w;
            *(float4*)&out[gm * 256 + n0 + tx * 4] = o;
        }
    }
}

// ---------------- logits: g_S = scale * q.k  (8q x 64k, 128 thr) ----------------
__global__ void __launch_bounds__(128) logits_kernel() {
    __shared__ float sm_qT[64 * 8];
    __shared__ float sm_kT[64 * 64];

    int k0 = blockIdx.x * 64;
    int q0 = blockIdx.y * 8;
    int t = threadIdx.x;
    int qp = t >> 5;
    int kg = t & 31;

    ull acc[2][8];
#pragma unroll
    for (int i = 0; i < 2; ++i)
#pragma unroll
        for (int h = 0; h < 8; ++h) acc[i][h] = 0ull;

#pragma unroll
    for (int c = 0; c < 4; ++c) {
#pragma unroll
        for (int j = 0; j < 4; ++j) {
            int idx = t + j * 128;
            int d = idx >> 3, ql = idx & 7;
            int gq = q0 + ql; if (gq > NQ - 1) gq = NQ - 1;
            sm_qT[d * 8 + ql] = g_q[gq * 256 + c * 64 + d];
        }
#pragma unroll
        for (int j = 0; j < 8; ++j) {
            int idx = t + j * 128;
            int d4 = idx >> 6, kr = idx & 63;
            float4 b = *(const float4*)&g_k[(k0 + kr) * 256 + c * 64 + d4 * 4];
            sm_kT[(d4 * 4 + 0) * 64 + kr] = b.x;
            sm_kT[(d4 * 4 + 1) * 64 + kr] = b.y;
            sm_kT[(d4 * 4 + 2) * 64 + kr] = b.z;
            sm_kT[(d4 * 4 + 3) * 64 + kr] = b.w;
        }
        __syncthreads();

#pragma unroll
        for (int half = 0; half < 2; ++half) {
            int h = c * 2 + half;
#pragma unroll 8
            for (int dl = 0; dl < 32; ++dl) {
                int d = half * 32 + dl;
                ull sv2 = *(const ull*)&sm_qT[d * 8 + qp * 2];
                float s0, s1; upk2(sv2, s0, s1);
                ull kp = *(const ull*)&sm_kT[d * 64 + kg * 2];
                fma2(acc[0][h], pk2(s0, s0), kp);
                fma2(acc[1][h], pk2(s1, s1), kp);
            }
        }
        __syncthreads();
    }

    const float scale = 0.17677669529663688f;
    ull sc = pk2(scale, scale);
#pragma unroll
    for (int i = 0; i < 2; ++i) {
        int gq = q0 + qp * 2 + i;
        if (gq < NQ) {
#pragma unroll
            for (int h = 0; h < 8; ++h) {
                ull v = mul2(acc[i][h], sc);
                float lo, hi; upk2(v, lo, hi);
                float2 o = {lo, hi};
                *(float2*)&g_S[(gq * 8 + h) * HW + k0 + kg * 2] = o;
            }
        }
    }
}

// ---------------- bias: R14 inner loop, plain stores to g_B/g_B2 ([q][h][k]) ----------------
// grid (16, 38, 2) = 1216; runs on the forked stream, only depends on prep.
__global__ void __launch_bounds__(128, 8) bias_kernel() {
    __shared__ float sm_s[64 * 8];   // [64f][8q]
    __shared__ float sm_t[64 * 64];  // [64f][64k] (negated t)
    __shared__ float sm_w[64 * 8];   // [64f][8h] natural W2 rows

    int k0 = blockIdx.x * 64;
    int q0 = blockIdx.y * 8;
    int fbase = blockIdx.z * 256;
    float* gB = (blockIdx.z == 0) ? g_B : g_B2;

    int t = threadIdx.x;
    int qp = t >> 5;
    int kg = t & 31;

    ulonglong2 acc_[2][2][2];
#pragma unroll
    for (int qi = 0; qi < 2; ++qi)
#pragma unroll
        for (int ki = 0; ki < 2; ++ki)
#pragma unroll
            for (int hh = 0; hh < 2; ++hh) { acc_[qi][ki][hh].x = 0ull; acc_[qi][ki][hh].y = 0ull; }

    for (int fc = 0; fc < 4; ++fc) {
        int f0 = fbase + fc * 64;
#pragma unroll
        for (int j = 0; j < 4; ++j) {
            int idx = t + j * 128;
            int fr = idx >> 3, ql = idx & 7;
            int gq = q0 + ql; if (gq > NQ - 1) gq = NQ - 1;
            sm_s[fr * 8 + ql] = g_s[(f0 + fr) * NQ + gq];
        }
#pragma unroll
        for (int j = 0; j < 8; ++j) {
            int idx = t + j * 128;
            int fr = idx >> 4, k4 = idx & 15;
            *(float4*)&sm_t[fr * 64 + k4 * 4] =
                *(const float4*)&g_t[(f0 + fr) * HW + k0 + k4 * 4];
        }
        {
            int fr = t >> 1, part = t & 1;
            *(float4*)&sm_w[fr * 8 + part * 4] =
                *(const float4*)&g_w2n[(f0 + fr) * 8 + part * 4];
        }
        __syncthreads();

#pragma unroll 8
        for (int fl = 0; fl < 64; ++fl) {
            ull sv2 = *(const ull*)&sm_s[fl * 8 + qp * 2];
            float s0, s1; upk2(sv2, s0, s1);
            ull tp = *(const ull*)&sm_t[fl * 64 + kg * 2];
            ull xa = add2(pk2(s0, s0), tp);
            ull xb = add2(pk2(s1, s1), tp);
            float x00, x01, x10, x11;
            upk2(xa, x00, x01);
            upk2(xb, x10, x11);
            x00 = fmaxf(x00, 0.0f); x01 = fmaxf(x01, 0.0f);
            x10 = fmaxf(x10, 0.0f); x11 = fmaxf(x11, 0.0f);
            ull xs00 = pk2(x00, x00), xs01 = pk2(x01, x01);
            ull xs10 = pk2(x10, x10), xs11 = pk2(x11, x11);
            ulonglong2 wA = *(const ulonglong2*)&sm_w[fl * 8];
            ulonglong2 wB = *(const ulonglong2*)&sm_w[fl * 8 + 4];
            fma2(acc_[0][0][0].x, xs00, wA.x); fma2(acc_[0][0][0].y, xs00, wA.y);
            fma2(acc_[0][0][1].x, xs00, wB.x); fma2(acc_[0][0][1].y, xs00, wB.y);
            fma2(acc_[0][1][0].x, xs01, wA.x); fma2(acc_[0][1][0].y, xs01, wA.y);
            fma2(acc_[0][1][1].x, xs01, wB.x); fma2(acc_[0][1][1].y, xs01, wB.y);
            fma2(acc_[1][0][0].x, xs10, wA.x); fma2(acc_[1][0][0].y, xs10, wA.y);
            fma2(acc_[1][0][1].x, xs10, wB.x); fma2(acc_[1][0][1].y, xs10, wB.y);
            fma2(acc_[1][1][0].x, xs11, wA.x); fma2(acc_[1][1][0].y, xs11, wA.y);
            fma2(acc_[1][1][1].x, xs11, wB.x); fma2(acc_[1][1][1].y, xs11, wB.y);
        }
        __syncthreads();
    }

    // transposed scalar stores to [q][h][k]
#pragma unroll
    for (int qi = 0; qi < 2; ++qi) {
        int gq = q0 + qp * 2 + qi;
        if (gq < NQ) {
#pragma unroll
            for (int ki = 0; ki < 2; ++ki) {
                int gk = k0 + kg * 2 + ki;
                float hv[8];
                upk2(acc_[qi][ki][0].x, hv[0], hv[1]);
                upk2(acc_[qi][ki][0].y, hv[2], hv[3]);
                upk2(acc_[qi][ki][1].x, hv[4], hv[5]);
                upk2(acc_[qi][ki][1].y, hv[6], hv[7]);
#pragma unroll
                for (int h = 0; h < 8; ++h) {
                    gB[(gq * 8 + h) * HW + gk] = hv[h];
                }
            }
        }
    }
}

// ---------------- softmax: probs = softmax(g_S + g_B + g_B2) -> g_S (R11, measured) ----------------
__global__ void __launch_bounds__(256) softmax_kernel() {
    int q = blockIdx.x;
    int warp = threadIdx.x >> 5, lane = threadIdx.x & 31;
    float4* rp = (float4*)&g_S[(q * 8 + warp) * 1024];
    const float4* bp = (const float4*)&g_B[(q * 8 + warp) * 1024];
    const float4* bp2 = (const float4*)&g_B2[(q * 8 + warp) * 1024];

    float4 r[8];
#pragma unroll
    for (int j = 0; j < 8; ++j) {
        float4 a = rp[lane + 32 * j];
        float4 b = bp[lane + 32 * j];
        float4 c = bp2[lane + 32 * j];
        r[j].x = a.x + b.x + c.x; r[j].y = a.y + b.y + c.y;
        r[j].z = a.z + b.z + c.z; r[j].w = a.w + b.w + c.w;
    }

    float m = -1e30f;
#pragma unroll
    for (int j = 0; j < 8; ++j) {
        m = fmaxf(m, fmaxf(fmaxf(r[j].x, r[j].y), fmaxf(r[j].z, r[j].w)));
    }
#pragma unroll
    for (int o = 16; o; o >>= 1) m = fmaxf(m, __shfl_xor_sync(0xffffffffu, m, o));

    float s = 0.0f;
#pragma unroll
    for (int j = 0; j < 8; ++j) {
        r[j].x = __expf(r[j].x - m); s += r[j].x;
        r[j].y = __expf(r[j].y - m); s += r[j].y;
        r[j].z = __expf(r[j].z - m); s += r[j].z;
        r[j].w = __expf(r[j].w - m); s += r[j].w;
    }
#pragma unroll
    for (int o = 16; o; o >>= 1) s += __shfl_xor_sync(0xffffffffu, s, o);
    float inv = 1.0f / s;

#pragma unroll
    for (int j = 0; j < 8; ++j) {
        r[j].x *= inv; r[j].y *= inv; r[j].z *= inv; r[j].w *= inv;
        rp[lane + 32 * j] = r[j];
    }
}

// ---------------- PV GEMM, k-split via z: grid (4, 38, 2) (R14, frozen) ----------------
__global__ void __launch_bounds__(128) pv_kernel() {
    __shared__ float Psm[16 * 64];
    __shared__ float vsm[64 * 64];

    int by = blockIdx.x;
    int q0 = blockIdx.y * 8;
    int zc = blockIdx.z;
    float* ctx = (zc == 0) ? g_ctx : g_ctx2;
    int t = threadIdx.x;
    int qg = t >> 5;
    int cp = t & 31;
    int h = cp >> 4;
    int cpl = cp & 15;

    ull acc2[2] = {0ull, 0ull};

    for (int kc = zc * 512; kc < zc * 512 + 512; kc += 64) {
#pragma unroll
        for (int it = 0; it < 2; ++it) {
            int idx = t + it * 128;
            int row = idx >> 4, kk4 = idx & 15;
            int q_l = row & 7, hh = row >> 3;
            int gq = q0 + q_l; if (gq > NQ - 1) gq = NQ - 1;
            *(float4*)&Psm[(hh * 8 + q_l) * 64 + kk4 * 4] =
                *(const float4*)&g_S[(gq * 8 + 2 * by + hh) * 1024 + kc + kk4 * 4];
        }
#pragma unroll
        for (int it = 0; it < 8; ++it) {
            int idx = t + it * 128;
            int row = idx >> 4, c4 = idx & 15;
            *(float4*)&vsm[row * 64 + c4 * 4] =
                *(const float4*)&g_v[(kc + row) * 256 + by * 64 + c4 * 4];
        }
        __syncthreads();

#pragma unroll 4
        for (int kk = 0; kk < 64; kk += 4) {
            float4 p0 = *(const float4*)&Psm[(h * 8 + qg * 2 + 0) * 64 + kk];
            float4 p1 = *(const float4*)&Psm[(h * 8 + qg * 2 + 1) * 64 + kk];
            float p0a[4] = {p0.x, p0.y, p0.z, p0.w};
            float p1a[4] = {p1.x, p1.y, p1.z, p1.w};
#pragma unroll
            for (int j = 0; j < 4; ++j) {
                ull vv = *(const ull*)&vsm[(kk + j) * 64 + h * 32 + cpl * 2];
                fma2(acc2[0], pk2(p0a[j], p0a[j]), vv);
                fma2(acc2[1], pk2(p1a[j], p1a[j]), vv);
            }
        }
        __syncthreads();
    }

#pragma unroll
    for (int i = 0; i < 2; ++i) {
        int gq = q0 + qg * 2 + i;
        if (gq < NQ) {
            float lo, hi;
            upk2(acc2[i], lo, hi);
            float2 o = {lo, hi};
            *(float2*)&ctx[gq * 256 + by * 64 + h * 32 + cpl * 2] = o;
        }
    }
}

// ---------------- out-proj GEMM: out = (ctxA + ctxB) @ WoT + bo (R14, frozen) ----------------
__global__ void __launch_bounds__(128) outproj_kernel(const float* __restrict__ bo,
                                                      float* __restrict__ out) {
    __shared__ float Csm[8 * 64];
    __shared__ float wsm[64 * 64];

    int by = blockIdx.x;
    int q0 = blockIdx.y * 8;
    int t = threadIdx.x;
    int qg = t >> 5;
    int cp = t & 31;

    ull acc2[2] = {0ull, 0ull};

    for (int kc = 0; kc < 256; kc += 64) {
        {
            int row = t >> 4, kk4 = t & 15;
            int gq = q0 + row; if (gq > NQ - 1) gq = NQ - 1;
            float4 a = *(const float4*)&g_ctx[gq * 256 + kc + kk4 * 4];
            float4 b = *(const float4*)&g_ctx2[gq * 256 + kc + kk4 * 4];
            a.x += b.x; a.y += b.y; a.z += b.z; a.w += b.w;
            *(float4*)&Csm[row * 64 + kk4 * 4] = a;
        }
#pragma unroll
        for (int it = 0; it < 8; ++it) {
            int idx = t + it * 128;
            int row = idx >> 4, c4 = idx & 15;
            *(float4*)&wsm[row * 64 + c4 * 4] =
                *(const float4*)&g_wot[(kc + row) * 256 + by * 64 + c4 * 4];
        }
        __syncthreads();

#pragma unroll 4
        for (int kk = 0; kk < 64; kk += 4) {
            float4 c0 = *(const float4*)&Csm[(qg * 2 + 0) * 64 + kk];
            float4 c1 = *(const float4*)&Csm[(qg * 2 + 1) * 64 + kk];
            float c0a[4] = {c0.x, c0.y, c0.z, c0.w};
            float c1a[4] = {c1.x, c1.y, c1.z, c1.w};
#pragma unroll
            for (int j = 0; j < 4; ++j) {
                ull ww = *(const ull*)&wsm[(kk + j) * 64 + cp * 2];
                fma2(acc2[0], pk2(c0a[j], c0a[j]), ww);
                fma2(acc2[1], pk2(c1a[j], c1a[j]), ww);
            }
        }
        __syncthreads();
    }

    float b0 = bo[by * 64 + cp * 2], b1 = bo[by * 64 + cp * 2 + 1];
#pragma unroll
    for (int i = 0; i < 2; ++i) {
        int gq = q0 + qg * 2 + i;
        if (gq < NQ) {
            float lo, hi;
            upk2(acc2[i], lo, hi);
            float2 o = {lo + b0, hi + b1};
            *(float2*)&out[gq * 256 + cp * 2 + by * 64] = o;
        }
    }
}

// ---------------- launch: fork bias onto a side stream while qkv+logits run ----------------
extern "C" void kernel_launch(void* const* d_in, const int* in_sizes, int n_in,
                              void* d_out, int out_size) {
    const float* raw_query = (const float*)d_in[0];
    const float* query_pos = (const float*)d_in[1];
    const float* ref_pts   = (const float*)d_in[2];
    const float* raw_src   = (const float*)d_in[3];
    const float* src_pos   = (const float*)d_in[4];
    const float* Wq = (const float*)d_in[5];
    const float* bq = (const float*)d_in[6];
    const float* Wk = (const float*)d_in[7];
    const float* bk = (const float*)d_in[8];
    const float* Wv = (const float*)d_in[9];
    const float* bv = (const float*)d_in[10];
    const float* Wo = (const float*)d_in[11];
    const float* bo = (const float*)d_in[12];
    const float* W1 = (const float*)d_in[13];
    const float* b1 = (const float*)d_in[14];
    const float* W2 = (const float*)d_in[15];
    float* out = (float*)d_out;

    // Side stream + events (created per call; leaked deliberately — kernel_launch
    // runs only a handful of times and these are host handles, not device memory).
    cudaStream_t s2;
    cudaStreamCreateWithFlags(&s2, cudaStreamNonBlocking);
    cudaEvent_t eFork, eJoin;
    cudaEventCreateWithFlags(&eFork, cudaEventDisableTiming);
    cudaEventCreateWithFlags(&eJoin, cudaEventDisableTiming);

    // 1. prep on main stream (feeds both branches)
    prep_kernel<<<512, 128>>>(ref_pts, W1, b1, W2, Wo);

    // fork: bias branch (depends only on prep tables)
    cudaEventRecord(eFork, 0);
    cudaStreamWaitEvent(s2, eFork, 0);
    bias_kernel<<<dim3(16, 38, 2), 128, 0, s2>>>();

    // main branch: qkv -> logits
    qkv_gemm_kernel<<<dim3(74, 4), 128>>>(raw_query, query_pos, raw_src, src_pos,
                                          Wq, bq, Wk, bk, Wv, bv);
    logits_kernel<<<dim3(16, 38), 128>>>();

    // join
    cudaEventRecord(eJoin, s2);
    cudaStreamWaitEvent(0, eJoin, 0);

    // tail on main stream
    softmax_kernel<<<300, 256>>>();
    pv_kernel<<<dim3(4, 38, 2), 128>>>();
    outproj_kernel<<<dim3(4, 38), 128>>>(bo, out);
}